// round 1
// baseline (speedup 1.0000x reference)
#include <cuda_runtime.h>
#include <math_constants.h>
#include <cstdint>

#define M_TOTAL 16384      // 4 * 4096 tokens
#define N_KEYS  4096
#define DHEAD   128
#define HDIM    1024
#define TOPK    8
#define EPS_F   1e-10f
#define SCALE_F 0.08838834764831845f   // 1/sqrt(128)

// Scratch (static device globals; no runtime allocation)
__device__ float g_scores[(size_t)M_TOTAL * N_KEYS];   // 256 MB
__device__ float g_logrel[N_KEYS];
__device__ float g_w[M_TOTAL * TOPK];
__device__ int   g_idx[M_TOTAL * TOPK];

// ---------------------------------------------------------------------------
// Kernel 0: logrel[n] = log(rel[n] + eps)
// ---------------------------------------------------------------------------
__global__ void logrel_kernel(const float* __restrict__ rel) {
    int i = blockIdx.x * blockDim.x + threadIdx.x;
    if (i < N_KEYS) g_logrel[i] = logf(rel[i] + EPS_F);
}

// ---------------------------------------------------------------------------
// Kernel 1: scores[m][n] = q[m] . k[n] + logrel[n]
// 128x128 block tile, 8x8 micro-tile per thread (256 threads),
// interleaved (stride-16) thread mapping, pad-129 smem rows => conflict-free LDS.
// ---------------------------------------------------------------------------
#define TM 128
#define TN 128
#define SROW (DHEAD + 1)   // 129 floats

__global__ __launch_bounds__(256, 1)
void score_kernel(const float* __restrict__ Q, const float* __restrict__ K) {
    extern __shared__ float smem[];
    float* Qs = smem;                  // [TM][SROW]
    float* Ks = smem + TM * SROW;      // [TN][SROW]
    float* lr = Ks + TN * SROW;        // [TN]

    const int tid = threadIdx.x;
    const int m0 = blockIdx.y * TM;
    const int n0 = blockIdx.x * TN;

    // Cooperative tile loads (float4 from gmem, scalar scatter to padded smem)
    #pragma unroll
    for (int t = tid; t < TM * DHEAD / 4; t += 256) {
        int r = t >> 5, c = (t & 31) << 2;
        float4 v = *(const float4*)(Q + (size_t)(m0 + r) * DHEAD + c);
        float* p = Qs + r * SROW + c;
        p[0] = v.x; p[1] = v.y; p[2] = v.z; p[3] = v.w;
    }
    #pragma unroll
    for (int t = tid; t < TN * DHEAD / 4; t += 256) {
        int r = t >> 5, c = (t & 31) << 2;
        float4 v = *(const float4*)(K + (size_t)(n0 + r) * DHEAD + c);
        float* p = Ks + r * SROW + c;
        p[0] = v.x; p[1] = v.y; p[2] = v.z; p[3] = v.w;
    }
    if (tid < TN) lr[tid] = g_logrel[n0 + tid];
    __syncthreads();

    const int tx = tid & 15;   // key group
    const int ty = tid >> 4;   // token group

    float acc[8][8];
    #pragma unroll
    for (int i = 0; i < 8; ++i)
        #pragma unroll
        for (int j = 0; j < 8; ++j) acc[i][j] = 0.0f;

    #pragma unroll 2
    for (int d = 0; d < DHEAD; ++d) {
        float qf[8], kf[8];
        #pragma unroll
        for (int i = 0; i < 8; ++i) qf[i] = Qs[(ty + 16 * i) * SROW + d];
        #pragma unroll
        for (int j = 0; j < 8; ++j) kf[j] = Ks[(tx + 16 * j) * SROW + d];
        #pragma unroll
        for (int i = 0; i < 8; ++i)
            #pragma unroll
            for (int j = 0; j < 8; ++j)
                acc[i][j] = fmaf(qf[i], kf[j], acc[i][j]);
    }

    #pragma unroll
    for (int i = 0; i < 8; ++i) {
        int m = m0 + ty + 16 * i;
        float* crow = g_scores + (size_t)m * N_KEYS + n0;
        #pragma unroll
        for (int j = 0; j < 8; ++j) {
            int n = tx + 16 * j;
            crow[n] = acc[i][j] + lr[n];
        }
    }
}

// ---------------------------------------------------------------------------
// Kernel 2: per-token top-8 (stable, descending, ties -> lowest index to match
// lax.top_k) + softmax of (score - logrel[idx]) * SCALE.
// One block (256 threads) per token.
// ---------------------------------------------------------------------------
__global__ __launch_bounds__(256)
void topk_kernel(float* __restrict__ w_out) {
    const int token = blockIdx.x;
    const int tid = threadIdx.x;
    __shared__ float s[N_KEYS];
    __shared__ float warpv[8];
    __shared__ int   warpi[8];
    __shared__ float topv[TOPK];
    __shared__ int   topi[TOPK];

    const float* srow = g_scores + (size_t)token * N_KEYS;
    #pragma unroll
    for (int i = tid; i < N_KEYS; i += 256) s[i] = srow[i];
    __syncthreads();

    for (int it = 0; it < TOPK; ++it) {
        float bv = -CUDART_INF_F;
        int   bi = N_KEYS;
        #pragma unroll
        for (int i = tid; i < N_KEYS; i += 256) {
            float v = s[i];
            if (v > bv) { bv = v; bi = i; }   // i ascending => first occurrence kept
        }
        // warp reduce (value desc, index asc tiebreak)
        #pragma unroll
        for (int o = 16; o > 0; o >>= 1) {
            float ov = __shfl_down_sync(0xffffffffu, bv, o);
            int   oi = __shfl_down_sync(0xffffffffu, bi, o);
            if (ov > bv || (ov == bv && oi < bi)) { bv = ov; bi = oi; }
        }
        if ((tid & 31) == 0) { warpv[tid >> 5] = bv; warpi[tid >> 5] = bi; }
        __syncthreads();
        if (tid == 0) {
            bv = warpv[0]; bi = warpi[0];
            #pragma unroll
            for (int wq = 1; wq < 8; ++wq) {
                if (warpv[wq] > bv || (warpv[wq] == bv && warpi[wq] < bi)) {
                    bv = warpv[wq]; bi = warpi[wq];
                }
            }
            topv[it] = bv; topi[it] = bi;
            s[bi] = -CUDART_INF_F;
        }
        __syncthreads();
    }

    if (tid == 0) {
        float sc[TOPK];
        float mx = -CUDART_INF_F;
        #pragma unroll
        for (int k = 0; k < TOPK; ++k) {
            // raw dot = biased score - bias; attention score = dot * SCALE
            sc[k] = (topv[k] - g_logrel[topi[k]]) * SCALE_F;
            mx = fmaxf(mx, sc[k]);
        }
        float sum = 0.0f;
        #pragma unroll
        for (int k = 0; k < TOPK; ++k) { sc[k] = expf(sc[k] - mx); sum += sc[k]; }
        float inv = 1.0f / sum;
        #pragma unroll
        for (int k = 0; k < TOPK; ++k) {
            float w = sc[k] * inv;
            w_out[(size_t)token * TOPK + k] = w;
            g_w[token * TOPK + k]   = w;
            g_idx[token * TOPK + k] = topi[k];
        }
    }
}

// ---------------------------------------------------------------------------
// Kernel 3: out[token][h] = sum_k w_k * values[idx_k][h]
// One block per token, 256 threads x float4 = 1024 columns.
// ---------------------------------------------------------------------------
__global__ __launch_bounds__(256)
void gather_kernel(const float* __restrict__ values, float* __restrict__ out) {
    const int token = blockIdx.x;
    const int h = threadIdx.x << 2;

    __shared__ float ws[TOPK];
    __shared__ int   is[TOPK];
    if (threadIdx.x < TOPK) {
        ws[threadIdx.x] = g_w[token * TOPK + threadIdx.x];
        is[threadIdx.x] = g_idx[token * TOPK + threadIdx.x];
    }
    __syncthreads();

    float4 acc = make_float4(0.f, 0.f, 0.f, 0.f);
    #pragma unroll
    for (int k = 0; k < TOPK; ++k) {
        float w = ws[k];
        const float4 v = *(const float4*)(values + (size_t)is[k] * HDIM + h);
        acc.x = fmaf(w, v.x, acc.x);
        acc.y = fmaf(w, v.y, acc.y);
        acc.z = fmaf(w, v.z, acc.z);
        acc.w = fmaf(w, v.w, acc.w);
    }
    *(float4*)(out + (size_t)token * HDIM + h) = acc;
}

// ---------------------------------------------------------------------------
extern "C" void kernel_launch(void* const* d_in, const int* in_sizes, int n_in,
                              void* d_out, int out_size) {
    const float* query = (const float*)d_in[0];   // [4,4096,128]
    const float* keys  = (const float*)d_in[1];   // [4096,128]
    const float* vals  = (const float*)d_in[2];   // [4096,1024]
    const float* rel   = (const float*)d_in[3];   // [4096]

    float* out   = (float*)d_out;                        // [4,4096,1024]
    float* w_out = out + (size_t)M_TOTAL * HDIM;         // [4,4096,8]

    const int smem_bytes = (TM + TN) * SROW * sizeof(float) + TN * sizeof(float);
    cudaFuncSetAttribute(score_kernel,
                         cudaFuncAttributeMaxDynamicSharedMemorySize, smem_bytes);

    logrel_kernel<<<(N_KEYS + 255) / 256, 256>>>(rel);
    score_kernel<<<dim3(N_KEYS / TN, M_TOTAL / TM), 256, smem_bytes>>>(query, keys);
    topk_kernel<<<M_TOTAL, 256>>>(w_out);
    gather_kernel<<<M_TOTAL, 256>>>(vals, out);
}

// round 2
// speedup vs baseline: 1.2033x; 1.2033x over previous
#include <cuda_runtime.h>
#include <math_constants.h>
#include <cstdint>

#define M_TOTAL 16384      // 4 * 4096 tokens
#define N_KEYS  4096
#define DHEAD   128
#define HDIM    1024
#define TOPK    8
#define EPS_F   1e-10f
#define SCALE_F 0.08838834764831845f   // 1/sqrt(128)

#define TM 128             // tokens per block
#define TN 128             // keys per tile
#define SROW 132           // padded row stride (floats): 4-aligned, conflict-free

// Scratch
__device__ float g_logrel[N_KEYS];
__device__ float g_w[M_TOTAL * TOPK];
__device__ int   g_idx[M_TOTAL * TOPK];

// ---------------------------------------------------------------------------
// Kernel 0: logrel[n] = log(rel[n] + eps)
// ---------------------------------------------------------------------------
__global__ void logrel_kernel(const float* __restrict__ rel) {
    int i = blockIdx.x * blockDim.x + threadIdx.x;
    if (i < N_KEYS) g_logrel[i] = logf(rel[i] + EPS_F);
}

// ---------------------------------------------------------------------------
// Kernel 1 (fused): scores + online top-8 + softmax.
// Block = 128 tokens, loops over 32 key tiles of 128.
//  compute phase: 8x8 micro-tile per thread (256 thr), float4 smem reads
//  topk phase:    2 threads per token keep running sorted top-8 in registers
//  final:         stable 2-list merge per token, softmax, store w+idx
// ---------------------------------------------------------------------------
__global__ __launch_bounds__(256, 1)
void fused_score_topk(const float* __restrict__ Q, const float* __restrict__ K,
                      float* __restrict__ w_out) {
    extern __shared__ float smem[];
    float* Qs  = smem;                    // [TM][SROW]
    float* Ks  = Qs + TM * SROW;          // [TN][SROW]  (reused as merge buf at end)
    float* Sb  = Ks + TN * SROW;          // [TM][SROW]  score tile
    float* lrS = Sb + TM * SROW;          // [TN]

    const int tid = threadIdx.x;
    const int m0  = blockIdx.x * TM;
    const int tx  = tid & 15;             // key group (compute phase)
    const int ty  = tid >> 4;             // token group (compute phase)

    // Persistent Q tile load (float4, stride-132 rows keep 16B alignment)
    #pragma unroll
    for (int t = tid; t < TM * DHEAD / 4; t += 256) {
        int r = t >> 5, c = (t & 31) << 2;
        float4 v = *(const float4*)(Q + (size_t)(m0 + r) * DHEAD + c);
        *(float4*)(Qs + r * SROW + c) = v;
    }

    // Running top-8 (sorted desc; strict-> insertion == lax.top_k stable order)
    float lv[TOPK];
    int   li[TOPK];
    #pragma unroll
    for (int k = 0; k < TOPK; ++k) { lv[k] = -CUDART_INF_F; li[k] = 0x7fffffff; }

    const int tok  = tid >> 1;            // token owned in topk phase
    const int half = tid & 1;             // which 64-key half of the tile

    for (int tile = 0; tile < N_KEYS / TN; ++tile) {
        const int n0 = tile * TN;
        __syncthreads();   // prev topk scan done before Ks/Sb rewritten

        // Load K tile + logrel tile
        #pragma unroll
        for (int t = tid; t < TN * DHEAD / 4; t += 256) {
            int r = t >> 5, c = (t & 31) << 2;
            float4 v = *(const float4*)(K + (size_t)(n0 + r) * DHEAD + c);
            *(float4*)(Ks + r * SROW + c) = v;
        }
        if (tid < TN) lrS[tid] = g_logrel[n0 + tid];
        __syncthreads();

        // Compute 128x128 score tile (8x8 per thread)
        float acc[8][8];
        #pragma unroll
        for (int i = 0; i < 8; ++i)
            #pragma unroll
            for (int j = 0; j < 8; ++j) acc[i][j] = 0.0f;

        #pragma unroll 2
        for (int d4 = 0; d4 < DHEAD / 4; ++d4) {
            float4 qv[8], kv[8];
            #pragma unroll
            for (int i = 0; i < 8; ++i)
                qv[i] = *(const float4*)(Qs + (ty + 16 * i) * SROW + 4 * d4);
            #pragma unroll
            for (int j = 0; j < 8; ++j)
                kv[j] = *(const float4*)(Ks + (tx + 16 * j) * SROW + 4 * d4);
            #pragma unroll
            for (int i = 0; i < 8; ++i)
                #pragma unroll
                for (int j = 0; j < 8; ++j) {
                    acc[i][j] = fmaf(qv[i].x, kv[j].x, acc[i][j]);
                    acc[i][j] = fmaf(qv[i].y, kv[j].y, acc[i][j]);
                    acc[i][j] = fmaf(qv[i].z, kv[j].z, acc[i][j]);
                    acc[i][j] = fmaf(qv[i].w, kv[j].w, acc[i][j]);
                }
        }

        // Biased scores -> smem tile
        #pragma unroll
        for (int i = 0; i < 8; ++i) {
            float* row = Sb + (ty + 16 * i) * SROW;
            #pragma unroll
            for (int j = 0; j < 8; ++j) {
                int n = tx + 16 * j;
                row[n] = acc[i][j] + lrS[n];
            }
        }
        __syncthreads();

        // Top-k scan: 2 threads per token, 64 keys each (float4 reads)
        const float* srow = Sb + tok * SROW + half * 64;
        #pragma unroll
        for (int c4 = 0; c4 < 16; ++c4) {
            float4 sv = *(const float4*)(srow + 4 * c4);
            float vs[4] = {sv.x, sv.y, sv.z, sv.w};
            #pragma unroll
            for (int e = 0; e < 4; ++e) {
                float v = vs[e];
                if (v > lv[TOPK - 1]) {
                    int gi = n0 + half * 64 + 4 * c4 + e;
                    lv[TOPK - 1] = v; li[TOPK - 1] = gi;
                    #pragma unroll
                    for (int s = TOPK - 1; s > 0; --s) {
                        if (lv[s] > lv[s - 1]) {
                            float tv = lv[s]; lv[s] = lv[s - 1]; lv[s - 1] = tv;
                            int   ti = li[s]; li[s] = li[s - 1]; li[s - 1] = ti;
                        } else break;
                    }
                }
            }
        }
    }
    __syncthreads();   // all scans done; Ks region now free for merge buffers

    // Dump per-thread lists: mval[tok][half][8], midx[tok][half][8] in Ks region
    float* mval = Ks;
    int*   midx = (int*)(Ks + TM * 2 * TOPK);
    #pragma unroll
    for (int k = 0; k < TOPK; ++k) {
        mval[(tok * 2 + half) * TOPK + k] = lv[k];
        midx[(tok * 2 + half) * TOPK + k] = li[k];
    }
    __syncthreads();

    // One thread per token: stable merge of the two sorted 8-lists, softmax
    if (tid < TM) {
        const float* va = mval + (tid * 2 + 0) * TOPK;
        const float* vb = mval + (tid * 2 + 1) * TOPK;
        const int*   xa = midx + (tid * 2 + 0) * TOPK;
        const int*   xb = midx + (tid * 2 + 1) * TOPK;
        float fv[TOPK]; int fi[TOPK];
        int ia = 0, ib = 0;
        #pragma unroll
        for (int k = 0; k < TOPK; ++k) {
            float A = va[ia], B = vb[ib];
            bool takeA = (A > B) || (A == B && xa[ia] < xb[ib]);
            if (takeA) { fv[k] = A; fi[k] = xa[ia]; ++ia; }
            else       { fv[k] = B; fi[k] = xb[ib]; ++ib; }
        }
        // softmax over (biased - logrel) * SCALE
        float sc[TOPK], mx = -CUDART_INF_F;
        #pragma unroll
        for (int k = 0; k < TOPK; ++k) {
            sc[k] = (fv[k] - g_logrel[fi[k]]) * SCALE_F;
            mx = fmaxf(mx, sc[k]);
        }
        float sum = 0.0f;
        #pragma unroll
        for (int k = 0; k < TOPK; ++k) { sc[k] = expf(sc[k] - mx); sum += sc[k]; }
        float inv = 1.0f / sum;
        const int token = m0 + tid;
        #pragma unroll
        for (int k = 0; k < TOPK; ++k) {
            float w = sc[k] * inv;
            w_out[(size_t)token * TOPK + k] = w;
            g_w[token * TOPK + k]   = w;
            g_idx[token * TOPK + k] = fi[k];
        }
    }
}

// ---------------------------------------------------------------------------
// Kernel 2: out[token][h] = sum_k w_k * values[idx_k][h]
// ---------------------------------------------------------------------------
__global__ __launch_bounds__(256)
void gather_kernel(const float* __restrict__ values, float* __restrict__ out) {
    const int token = blockIdx.x;
    const int h = threadIdx.x << 2;

    __shared__ float ws[TOPK];
    __shared__ int   is[TOPK];
    if (threadIdx.x < TOPK) {
        ws[threadIdx.x] = g_w[token * TOPK + threadIdx.x];
        is[threadIdx.x] = g_idx[token * TOPK + threadIdx.x];
    }
    __syncthreads();

    float4 acc = make_float4(0.f, 0.f, 0.f, 0.f);
    #pragma unroll
    for (int k = 0; k < TOPK; ++k) {
        float w = ws[k];
        const float4 v = *(const float4*)(values + (size_t)is[k] * HDIM + h);
        acc.x = fmaf(w, v.x, acc.x);
        acc.y = fmaf(w, v.y, acc.y);
        acc.z = fmaf(w, v.z, acc.z);
        acc.w = fmaf(w, v.w, acc.w);
    }
    *(float4*)(out + (size_t)token * HDIM + h) = acc;
}

// ---------------------------------------------------------------------------
extern "C" void kernel_launch(void* const* d_in, const int* in_sizes, int n_in,
                              void* d_out, int out_size) {
    const float* query = (const float*)d_in[0];   // [4,4096,128]
    const float* keys  = (const float*)d_in[1];   // [4096,128]
    const float* vals  = (const float*)d_in[2];   // [4096,1024]
    const float* rel   = (const float*)d_in[3];   // [4096]

    float* out   = (float*)d_out;                        // [4,4096,1024]
    float* w_out = out + (size_t)M_TOTAL * HDIM;         // [4,4096,8]

    const int smem_bytes = (3 * TM * SROW + TN) * sizeof(float);  // ~203 KB
    static int configured = -1;
    if (configured < 0) {
        cudaFuncSetAttribute(fused_score_topk,
                             cudaFuncAttributeMaxDynamicSharedMemorySize, smem_bytes);
        configured = 1;
    }

    logrel_kernel<<<(N_KEYS + 255) / 256, 256>>>(rel);
    fused_score_topk<<<M_TOTAL / TM, 256, smem_bytes>>>(query, keys, w_out);
    gather_kernel<<<M_TOTAL, 256>>>(vals, out);
}